// round 2
// baseline (speedup 1.0000x reference)
#include <cuda_runtime.h>

#define BB 8
#define NN 2048
#define FF 256
#define ALPHA 0.2f

typedef unsigned long long u64;

// Scratch (allocation-free rule: __device__ globals)
__device__ float g_Wh[BB * NN * FF];   // 16 MB
__device__ float g_WT[FF * FF];        // W transposed: [k][o]
__device__ float g_s1[BB * NN];
__device__ float g_s2[BB * NN];

// ---- packed f32x2 helpers (bit-exact fp32, 2 FMAs per instruction) --------
__device__ __forceinline__ void ffma2(u64& d, u64 a, u64 b) {
    asm("fma.rn.f32x2 %0, %1, %2, %0;" : "+l"(d) : "l"(a), "l"(b));
}
__device__ __forceinline__ u64 pack2(float lo, float hi) {
    u64 r; asm("mov.b64 %0, {%1, %2};" : "=l"(r) : "f"(lo), "f"(hi)); return r;
}
__device__ __forceinline__ float2 unpack2(u64 v) {
    float2 r; asm("mov.b64 {%0, %1}, %2;" : "=f"(r.x), "=f"(r.y) : "l"(v)); return r;
}

// ---------------------------------------------------------------------------
// K0: transpose W [F_OUT, F_IN] -> g_WT [F_IN, F_OUT]   (tiny)
// ---------------------------------------------------------------------------
__global__ void transpose_W(const float* __restrict__ W) {
    __shared__ float tile[32][33];
    int k0 = blockIdx.x * 32;
    int o0 = blockIdx.y * 32;
    int lx = threadIdx.x & 31;
    int ly = threadIdx.x >> 5;
#pragma unroll
    for (int s = 0; s < 32; s += 8)
        tile[ly + s][lx] = W[(o0 + ly + s) * FF + (k0 + lx)];
    __syncthreads();
#pragma unroll
    for (int s = 0; s < 32; s += 8)
        g_WT[(k0 + ly + s) * FF + (o0 + lx)] = tile[lx][ly + s];
}

// ---------------------------------------------------------------------------
// K1: Wh = h @ W^T, 64x256 block tile, 8x8 micro-tile via f32x2.
// ---------------------------------------------------------------------------
__global__ __launch_bounds__(256) void gemm_Wh(const float* __restrict__ h) {
    __shared__ float hs[64][32];     // [row][k]
    __shared__ float ws[32][256];    // [k][o]
    const int row0 = blockIdx.x * 64;
    const int t  = threadIdx.x;
    const int ty = t >> 5, tx = t & 31;
    const int r0 = ty * 8, o0 = tx * 8;

    u64 acc[8][4];
#pragma unroll
    for (int i = 0; i < 8; i++)
#pragma unroll
        for (int j = 0; j < 4; j++) acc[i][j] = 0ull;

    for (int k0 = 0; k0 < FF; k0 += 32) {
        {
            float4* dst = (float4*)hs;
#pragma unroll
            for (int s = 0; s < 2; s++) {
                int v = t + 256 * s;
                int row = v >> 3, c = v & 7;
                dst[v] = ((const float4*)(h + (size_t)(row0 + row) * FF + k0))[c];
            }
        }
        {
            float4* dst = (float4*)ws;
#pragma unroll
            for (int s = 0; s < 8; s++) {
                int v = t + 256 * s;
                int kk = v >> 6, c = v & 63;
                dst[v] = ((const float4*)(g_WT + (size_t)(k0 + kk) * FF))[c];
            }
        }
        __syncthreads();

#pragma unroll 8
        for (int kk = 0; kk < 32; kk++) {
            ulonglong2 wA = *(const ulonglong2*)&ws[kk][o0];
            ulonglong2 wB = *(const ulonglong2*)&ws[kk][o0 + 4];
            u64 wv[4] = {wA.x, wA.y, wB.x, wB.y};
#pragma unroll
            for (int i = 0; i < 8; i++) {
                float a = hs[r0 + i][kk];          // broadcast
                u64 aa = pack2(a, a);
#pragma unroll
                for (int j = 0; j < 4; j++) ffma2(acc[i][j], aa, wv[j]);
            }
        }
        __syncthreads();
    }

#pragma unroll
    for (int i = 0; i < 8; i++) {
        float2 v0 = unpack2(acc[i][0]), v1 = unpack2(acc[i][1]);
        float2 v2 = unpack2(acc[i][2]), v3 = unpack2(acc[i][3]);
        float* dst = g_Wh + (size_t)(row0 + r0 + i) * FF + o0;
        *(float4*)(dst)     = make_float4(v0.x, v0.y, v1.x, v1.y);
        *(float4*)(dst + 4) = make_float4(v2.x, v2.y, v3.x, v3.y);
    }
}

// ---------------------------------------------------------------------------
// K2: s1/s2 row dots. One warp per row.
// ---------------------------------------------------------------------------
__global__ void compute_s(const float* __restrict__ a) {
    int gw = (blockIdx.x * blockDim.x + threadIdx.x) >> 5;
    int lane = threadIdx.x & 31;
    if (gw >= BB * NN) return;
    const float4* whr = (const float4*)(g_Wh + (size_t)gw * FF);
    const float4* a1v = (const float4*)a;
    const float4* a2v = ((const float4*)a) + 64;
    float s1 = 0.0f, s2 = 0.0f;
#pragma unroll
    for (int s = 0; s < 2; s++) {
        float4 v  = whr[lane * 2 + s];
        float4 c1 = a1v[lane * 2 + s];
        float4 c2 = a2v[lane * 2 + s];
        s1 += v.x * c1.x + v.y * c1.y + v.z * c1.z + v.w * c1.w;
        s2 += v.x * c2.x + v.y * c2.y + v.z * c2.z + v.w * c2.w;
    }
#pragma unroll
    for (int off = 16; off; off >>= 1) {
        s1 += __shfl_xor_sync(0xffffffffu, s1, off);
        s2 += __shfl_xor_sync(0xffffffffu, s2, off);
    }
    if (lane == 0) { g_s1[gw] = s1; g_s2[gw] = s2; }
}

// ---------------------------------------------------------------------------
// K3: attention, f32x2 stage B.
// Dynamic smem layout:
//   whs  : float [32][256]                  32768 B
//   ps2  : float2[64][33]  (duplicated p)   16896 B
//   s2s  : float [32]                         128 B
//   ls   : float [64]                         256 B
// ---------------------------------------------------------------------------
#define SMEM_WHS   0
#define SMEM_PS2   (32 * 256 * 4)
#define SMEM_S2S   (SMEM_PS2 + 64 * 33 * 8)
#define SMEM_LS    (SMEM_S2S + 32 * 4)
#define SMEM_TOTAL (SMEM_LS + 64 * 4)

__global__ __launch_bounds__(256, 2) void attn(const int* __restrict__ adj,
                                               float* __restrict__ out) {
    extern __shared__ char smem[];
    float  (*whs)[256] = (float(*)[256])(smem + SMEM_WHS);
    float2 (*ps2)[33]  = (float2(*)[33])(smem + SMEM_PS2);
    float* s2s = (float*)(smem + SMEM_S2S);
    float* ls  = (float*)(smem + SMEM_LS);

    const int b  = blockIdx.y;
    const int i0 = blockIdx.x * 64;
    const int t  = threadIdx.x;
    const int ty = t >> 5, tx = t & 31;
    const int r0 = ty * 8, f0 = tx * 8;

    // stage-A mapping: 4 threads per row, 8 j's each
    const int arow = t >> 2;
    const int ajl  = (t & 3) * 8;
    const float s1v = g_s1[(size_t)b * NN + i0 + arow];
    const int* adjrow = adj + ((size_t)b * NN + i0 + arow) * NN;

    if (t < 64) ls[t] = 0.0f;

    u64 acc[8][4];
#pragma unroll
    for (int i = 0; i < 8; i++)
#pragma unroll
        for (int j = 0; j < 4; j++) acc[i][j] = 0ull;

    for (int j0 = 0; j0 < NN; j0 += 32) {
        __syncthreads();  // previous stage B done before overwriting whs/ps2/s2s

        if (t < 32) s2s[t] = g_s2[(size_t)b * NN + j0 + t];
        {
            const float4* src = (const float4*)(g_Wh + ((size_t)b * NN + j0) * FF);
            float4* dst = (float4*)whs;   // 2048 float4, 8 per thread
#pragma unroll
            for (int s = 0; s < 8; s++) dst[t + 256 * s] = src[t + 256 * s];
        }
        __syncthreads();  // s2s/whs visible

        // ---- stage A: masked p-tile, stored duplicated (p,p) ----
        {
            int4 av0 = *(const int4*)(adjrow + j0 + ajl);
            int4 av1 = *(const int4*)(adjrow + j0 + ajl + 4);
            int ad[8] = {av0.x, av0.y, av0.z, av0.w, av1.x, av1.y, av1.z, av1.w};
            float psum = 0.0f;
            float2* prow = &ps2[arow][ajl];
#pragma unroll
            for (int s = 0; s < 8; s++) {
                float x = s1v + s2s[ajl + s];
                float e = (x > 0.0f) ? x : ALPHA * x;
                float p = ad[s] ? __expf(e) : 0.0f;
                prow[s] = make_float2(p, p);
                psum += p;
            }
            psum += __shfl_xor_sync(0xffffffffu, psum, 1);
            psum += __shfl_xor_sync(0xffffffffu, psum, 2);
            if ((t & 3) == 0) ls[arow] += psum;
        }
        __syncthreads();  // ps2 ready

        // ---- stage B: acc += p * Wh  (f32x2: 32 FFMA2 + 10 LDS per jj) ----
#pragma unroll 4
        for (int jj = 0; jj < 32; jj++) {
            ulonglong2 wA = *(const ulonglong2*)&whs[jj][f0];
            ulonglong2 wB = *(const ulonglong2*)&whs[jj][f0 + 4];
            u64 wv[4] = {wA.x, wA.y, wB.x, wB.y};
#pragma unroll
            for (int i = 0; i < 8; i++) {
                u64 pp = *(const u64*)&ps2[r0 + i][jj];   // broadcast, already (p,p)
#pragma unroll
                for (int j = 0; j < 4; j++) ffma2(acc[i][j], pp, wv[j]);
            }
        }
    }

    // epilogue: out = acc / l
#pragma unroll
    for (int i = 0; i < 8; i++) {
        float inv = 1.0f / ls[r0 + i];
        float2 v0 = unpack2(acc[i][0]), v1 = unpack2(acc[i][1]);
        float2 v2 = unpack2(acc[i][2]), v3 = unpack2(acc[i][3]);
        float* dst = out + ((size_t)b * NN + i0 + r0 + i) * FF + f0;
        *(float4*)(dst)     = make_float4(v0.x * inv, v0.y * inv, v1.x * inv, v1.y * inv);
        *(float4*)(dst + 4) = make_float4(v2.x * inv, v2.y * inv, v3.x * inv, v3.y * inv);
    }
}

// ---------------------------------------------------------------------------
extern "C" void kernel_launch(void* const* d_in, const int* in_sizes, int n_in,
                              void* d_out, int out_size) {
    const float* h   = (const float*)d_in[0];
    const int*   adj = (const int*)d_in[1];
    const float* W   = (const float*)d_in[2];
    const float* a   = (const float*)d_in[3];
    float* out = (float*)d_out;

    cudaFuncSetAttribute(attn, cudaFuncAttributeMaxDynamicSharedMemorySize, SMEM_TOTAL);

    transpose_W<<<dim3(FF / 32, FF / 32), 256>>>(W);
    gemm_Wh<<<(BB * NN) / 64, 256>>>(h);
    compute_s<<<(BB * NN) / 8, 256>>>(a);
    attn<<<dim3(NN / 64, BB), 256, SMEM_TOTAL>>>(adj, out);
}

// round 5
// speedup vs baseline: 2.4456x; 2.4456x over previous
#include <cuda_runtime.h>
#include <cstdint>

#define BB 8
#define NN 2048
#define FF 256
#define ALPHA 0.2f

// Scratch (allocation-free rule: __device__ globals)
__device__ float g_Wh[BB * NN * FF];   // 16 MB
__device__ float g_WT[FF * FF];        // W transposed: [k][o]
__device__ float g_s1[BB * NN];
__device__ float g_s2[BB * NN];

__device__ __forceinline__ float to_tf32(float x) {
    uint32_t r; asm("cvt.rna.tf32.f32 %0, %1;" : "=r"(r) : "f"(x));
    return __uint_as_float(r);
}

// ---------------------------------------------------------------------------
// K0: transpose W [F_OUT, F_IN] -> g_WT [F_IN, F_OUT]   (tiny)
// ---------------------------------------------------------------------------
__global__ void transpose_W(const float* __restrict__ W) {
    __shared__ float tile[32][33];
    int k0 = blockIdx.x * 32;
    int o0 = blockIdx.y * 32;
    int lx = threadIdx.x & 31;
    int ly = threadIdx.x >> 5;
#pragma unroll
    for (int s = 0; s < 32; s += 8)
        tile[ly + s][lx] = W[(o0 + ly + s) * FF + (k0 + lx)];
    __syncthreads();
#pragma unroll
    for (int s = 0; s < 32; s += 8)
        g_WT[(k0 + ly + s) * FF + (o0 + lx)] = tile[lx][ly + s];
}

// ---------------------------------------------------------------------------
// K1: Wh = h @ W^T  (fp32 scalar, R1-proven)
// ---------------------------------------------------------------------------
__global__ __launch_bounds__(256) void gemm_Wh(const float* __restrict__ h) {
    __shared__ float hs[64][32];
    __shared__ float ws[32][256];
    const int row0 = blockIdx.x * 64;
    const int t  = threadIdx.x;
    const int ty = t >> 5, tx = t & 31;
    const int r0 = ty * 8, o0 = tx * 8;

    float acc[8][8];
#pragma unroll
    for (int i = 0; i < 8; i++)
#pragma unroll
        for (int j = 0; j < 8; j++) acc[i][j] = 0.0f;

    for (int k0 = 0; k0 < FF; k0 += 32) {
        {
            float4* dst = (float4*)hs;
#pragma unroll
            for (int s = 0; s < 2; s++) {
                int v = t + 256 * s;
                int row = v >> 3, c = v & 7;
                dst[v] = ((const float4*)(h + (size_t)(row0 + row) * FF + k0))[c];
            }
        }
        {
            float4* dst = (float4*)ws;
#pragma unroll
            for (int s = 0; s < 8; s++) {
                int v = t + 256 * s;
                int kk = v >> 6, c = v & 63;
                dst[v] = ((const float4*)(g_WT + (size_t)(k0 + kk) * FF))[c];
            }
        }
        __syncthreads();

#pragma unroll 8
        for (int kk = 0; kk < 32; kk++) {
            float av[8];
#pragma unroll
            for (int i = 0; i < 8; i++) av[i] = hs[r0 + i][kk];
            float4 w0 = *(const float4*)&ws[kk][o0];
            float4 w1 = *(const float4*)&ws[kk][o0 + 4];
            float bv[8] = {w0.x, w0.y, w0.z, w0.w, w1.x, w1.y, w1.z, w1.w};
#pragma unroll
            for (int i = 0; i < 8; i++)
#pragma unroll
                for (int j = 0; j < 8; j++) acc[i][j] += av[i] * bv[j];
        }
        __syncthreads();
    }

#pragma unroll
    for (int i = 0; i < 8; i++) {
        float* dst = g_Wh + (size_t)(row0 + r0 + i) * FF + o0;
        *(float4*)(dst)     = make_float4(acc[i][0], acc[i][1], acc[i][2], acc[i][3]);
        *(float4*)(dst + 4) = make_float4(acc[i][4], acc[i][5], acc[i][6], acc[i][7]);
    }
}

// ---------------------------------------------------------------------------
// K2: s1/s2 row dots. One warp per row.
// ---------------------------------------------------------------------------
__global__ void compute_s(const float* __restrict__ a) {
    int gw = (blockIdx.x * blockDim.x + threadIdx.x) >> 5;
    int lane = threadIdx.x & 31;
    if (gw >= BB * NN) return;
    const float4* whr = (const float4*)(g_Wh + (size_t)gw * FF);
    const float4* a1v = (const float4*)a;
    const float4* a2v = ((const float4*)a) + 64;
    float s1 = 0.0f, s2 = 0.0f;
#pragma unroll
    for (int s = 0; s < 2; s++) {
        float4 v  = whr[lane * 2 + s];
        float4 c1 = a1v[lane * 2 + s];
        float4 c2 = a2v[lane * 2 + s];
        s1 += v.x * c1.x + v.y * c1.y + v.z * c1.z + v.w * c1.w;
        s2 += v.x * c2.x + v.y * c2.y + v.z * c2.z + v.w * c2.w;
    }
#pragma unroll
    for (int off = 16; off; off >>= 1) {
        s1 += __shfl_xor_sync(0xffffffffu, s1, off);
        s2 += __shfl_xor_sync(0xffffffffu, s2, off);
    }
    if (lane == 0) { g_s1[gw] = s1; g_s2[gw] = s2; }
}

// ---------------------------------------------------------------------------
// K3: attention via tf32 mma.sync.m16n8k8.
// Block: 64 rows x 256 feats, j-tiles of 64.
// Warp mapping: 8 warps = 8 feat-groups of 32 cols; each warp covers all 64
// rows (4 row-groups looped) -> unique B fragments per warp, 1.5 LDS/mma.
// smem (dynamic):
//   whs : float[64][264]  tf32 Wh tile (j-major)   67584 B
//   ps  : float[64][68]   tf32 p tile              17408 B   (68%32=4 -> A-loads conflict-free)
//   s2s : float[64], ls : float[64]                  512 B
// ---------------------------------------------------------------------------
#define WHS_STRIDE 264
#define PS_STRIDE  68
#define SMEM_WHS   0
#define SMEM_PS    (64 * WHS_STRIDE * 4)
#define SMEM_S2S   (SMEM_PS + 64 * PS_STRIDE * 4)
#define SMEM_LS    (SMEM_S2S + 64 * 4)
#define SMEM_TOTAL (SMEM_LS + 64 * 4)

__device__ __forceinline__ void mma_tf32(float* d,
                                         uint32_t a0, uint32_t a1, uint32_t a2, uint32_t a3,
                                         uint32_t b0, uint32_t b1) {
    asm volatile("mma.sync.aligned.m16n8k8.row.col.f32.tf32.tf32.f32 "
                 "{%0,%1,%2,%3}, {%4,%5,%6,%7}, {%8,%9}, {%0,%1,%2,%3};"
                 : "+f"(d[0]), "+f"(d[1]), "+f"(d[2]), "+f"(d[3])
                 : "r"(a0), "r"(a1), "r"(a2), "r"(a3), "r"(b0), "r"(b1));
}

__global__ __launch_bounds__(256, 2) void attn(const int* __restrict__ adj,
                                               float* __restrict__ out) {
    extern __shared__ char smem[];
    float (*whs)[WHS_STRIDE] = (float(*)[WHS_STRIDE])(smem + SMEM_WHS);
    float (*ps)[PS_STRIDE]   = (float(*)[PS_STRIDE])(smem + SMEM_PS);
    float* s2s = (float*)(smem + SMEM_S2S);
    float* ls  = (float*)(smem + SMEM_LS);

    const int b  = blockIdx.y;
    const int i0 = blockIdx.x * 64;
    const int t  = threadIdx.x;
    const int w  = t >> 5;
    const int lane = t & 31;
    const int gid  = lane >> 2;       // 0..7
    const int tig  = lane & 3;        // 0..3
    const int nbase = w * 32;         // this warp's 32 output columns

    // stage-A mapping: 4 threads per row, 16 j's each
    const int arow = t >> 2;
    const int ajl  = (t & 3) * 16;
    const float s1v = g_s1[(size_t)b * NN + i0 + arow];
    const int* adjrow = adj + ((size_t)b * NN + i0 + arow) * NN;

    if (t < 64) ls[t] = 0.0f;

    float d[4][4][4];   // [row-group][n-tile][frag] = 64 regs
#pragma unroll
    for (int rg = 0; rg < 4; rg++)
#pragma unroll
        for (int nt = 0; nt < 4; nt++)
#pragma unroll
            for (int c = 0; c < 4; c++) d[rg][nt][c] = 0.0f;

    for (int j0 = 0; j0 < NN; j0 += 64) {
        __syncthreads();  // prev stage B done (and ls init on first iter)

        // ---- fill whs (tf32-rounded) + s2s ----
        if (t < 64) s2s[t] = g_s2[(size_t)b * NN + j0 + t];
        {
            const float4* src = (const float4*)(g_Wh + ((size_t)b * NN + j0) * FF);
#pragma unroll
            for (int s = 0; s < 16; s++) {
                int v = t + 256 * s;
                int r = v >> 6, c = (v & 63) * 4;
                float4 x = src[v];
                x.x = to_tf32(x.x); x.y = to_tf32(x.y);
                x.z = to_tf32(x.z); x.w = to_tf32(x.w);
                *(float4*)&whs[r][c] = x;
            }
        }
        __syncthreads();

        // ---- stage A: masked tf32 p-tile + exact row sums ----
        {
            float psum = 0.0f;
#pragma unroll
            for (int q = 0; q < 4; q++) {
                int4 av = *(const int4*)(adjrow + j0 + ajl + q * 4);
                int ad[4] = {av.x, av.y, av.z, av.w};
                float pv[4];
#pragma unroll
                for (int s = 0; s < 4; s++) {
                    float x = s1v + s2s[ajl + q * 4 + s];
                    float e = (x > 0.0f) ? x : ALPHA * x;
                    float p = ad[s] ? __expf(e) : 0.0f;
                    psum += p;
                    pv[s] = to_tf32(p);
                }
                *(float4*)&ps[arow][ajl + q * 4] =
                    make_float4(pv[0], pv[1], pv[2], pv[3]);
            }
            psum += __shfl_xor_sync(0xffffffffu, psum, 1);
            psum += __shfl_xor_sync(0xffffffffu, psum, 2);
            if ((t & 3) == 0) ls[arow] += psum;
        }
        __syncthreads();  // ps/whs ready

        // ---- stage B: tensor-core PV (B-frags once per k, A-frags per rg) ----
        const uint32_t* psu  = (const uint32_t*)(smem + SMEM_PS);
        const uint32_t* whsu = (const uint32_t*)(smem + SMEM_WHS);
#pragma unroll
        for (int kk = 0; kk < 8; kk++) {
            const int k = kk * 8;
            uint32_t bv[4][2];
            const uint32_t* brow0 = whsu + (k + tig) * WHS_STRIDE + nbase + gid;
            const uint32_t* brow1 = whsu + (k + 4 + tig) * WHS_STRIDE + nbase + gid;
#pragma unroll
            for (int nt = 0; nt < 4; nt++) {
                bv[nt][0] = brow0[nt * 8];
                bv[nt][1] = brow1[nt * 8];
            }
#pragma unroll
            for (int rg = 0; rg < 4; rg++) {
                const int ra = rg * 16 + gid;
                uint32_t a0 = psu[ra * PS_STRIDE + k + tig];
                uint32_t a1 = psu[(ra + 8) * PS_STRIDE + k + tig];
                uint32_t a2 = psu[ra * PS_STRIDE + k + 4 + tig];
                uint32_t a3 = psu[(ra + 8) * PS_STRIDE + k + 4 + tig];
#pragma unroll
                for (int nt = 0; nt < 4; nt++)
                    mma_tf32(d[rg][nt], a0, a1, a2, a3, bv[nt][0], bv[nt][1]);
            }
        }
    }

    // ---- epilogue: divide by row sums, store ----
#pragma unroll
    for (int rg = 0; rg < 4; rg++) {
        const int ra = rg * 16 + gid;
        float inva = 1.0f / ls[ra];
        float invb = 1.0f / ls[ra + 8];
        float* outa = out + ((size_t)b * NN + i0 + ra) * FF;
        float* outb = outa + (size_t)8 * FF;
#pragma unroll
        for (int nt = 0; nt < 4; nt++) {
            int col = nbase + nt * 8 + 2 * tig;
            *(float2*)(outa + col) = make_float2(d[rg][nt][0] * inva, d[rg][nt][1] * inva);
            *(float2*)(outb + col) = make_float2(d[rg][nt][2] * invb, d[rg][nt][3] * invb);
        }
    }
}

// ---------------------------------------------------------------------------
extern "C" void kernel_launch(void* const* d_in, const int* in_sizes, int n_in,
                              void* d_out, int out_size) {
    const float* h   = (const float*)d_in[0];
    const int*   adj = (const int*)d_in[1];
    const float* W   = (const float*)d_in[2];
    const float* a   = (const float*)d_in[3];
    float* out = (float*)d_out;

    cudaFuncSetAttribute(attn, cudaFuncAttributeMaxDynamicSharedMemorySize, SMEM_TOTAL);

    transpose_W<<<dim3(FF / 32, FF / 32), 256>>>(W);
    gemm_Wh<<<(BB * NN) / 64, 256>>>(h);
    compute_s<<<(BB * NN) / 8, 256>>>(a);
    attn<<<dim3(NN / 64, BB), 256, SMEM_TOTAL>>>(adj, out);
}